// round 14
// baseline (speedup 1.0000x reference)
#include <cuda_runtime.h>
#include <cuda_bf16.h>
#include <cuda_fp16.h>
#include <math.h>
#include <float.h>
#include <stdint.h>

#define BB 4
#define LL 2048
#define DD 256

// ---------------- device scratch (allocation-free rule) ----------------
__device__ float g_c[DD];                              // bv @ Wo + bo
__device__ __half g_WTf16[DD * DD];                    // (Wv@Wo)^T fp16
__device__ __half g_valf16[BB * LL * DD];              // value fp16 [8192][256]
__device__ __half g_V2Tf16[DD * BB * LL];              // V2^T fp16 [256][8192]

// ---------------- helpers ----------------
__device__ __forceinline__ uint32_t smem_u32(const void* p) {
    uint32_t a;
    asm("{ .reg .u64 t; cvta.to.shared.u64 t, %1; cvt.u32.u64 %0, t; }" : "=r"(a) : "l"(p));
    return a;
}
#define CP_ASYNC16(sm, g) \
    asm volatile("cp.async.cg.shared.global [%0], [%1], 16;" :: "r"(sm), "l"(g))
#define CP_COMMIT() asm volatile("cp.async.commit_group;")
#define CP_WAITG(n) asm volatile("cp.async.wait_group %0;" :: "n"(n))

#define LDSM4(r0, r1, r2, r3, addr)                                            \
    asm volatile("ldmatrix.sync.aligned.m8n8.x4.shared.b16 {%0,%1,%2,%3}, [%4];" \
                 : "=r"(r0), "=r"(r1), "=r"(r2), "=r"(r3) : "r"(addr))

#define MMA_F16(d, a, b0, b1)                                                    \
    asm volatile("mma.sync.aligned.m16n8k16.row.col.f32.f16.f16.f32 "            \
                 "{%0,%1,%2,%3},{%4,%5,%6,%7},{%8,%9},{%0,%1,%2,%3};"            \
                 : "+f"((d)[0]), "+f"((d)[1]), "+f"((d)[2]), "+f"((d)[3])        \
                 : "r"((a)[0]), "r"((a)[1]), "r"((a)[2]), "r"((a)[3]),           \
                   "r"(b0), "r"(b1))

#define SWX(row, colb) ((row) * 128 + ((colb) ^ (((row) & 7) << 4)))

// ---------------------------------------------------------------------------
// Kernel 1 (heterogeneous):
//   blocks [0,33):  W rows / bias, Wo streamed through a 4-stage x 8-row
//                   cp.async pipeline (depth-3 outstanding).
//   blocks [33,33+2048): value fp32 -> fp16.
// ---------------------------------------------------------------------------
__global__ void k_pre(const float* __restrict__ Wv, const float* __restrict__ Wo,
                      const float* __restrict__ bv, const float* __restrict__ bo,
                      const float4* __restrict__ v) {
    const int blk = blockIdx.x;
    const int j = threadIdx.x;
    if (blk < 33) {
        __shared__ float sW[8][DD];            // Wv rows (or bv in sW[0])
        __shared__ float sWo[4][8][DD];        // 4 stages x 8 rows (32KB)
        const bool isbias = (blk == 32);
        const int i0 = blk * 8;
        const uint32_t swo = smem_u32(&sWo[0][0][0]);

        // prologue: stage chunks 0..2 (8 rows x 1KB each; 2 x 16B per thread)
#pragma unroll
        for (int c0 = 0; c0 < 3; c0++) {
#pragma unroll
            for (int i = 0; i < 2; i++) {
                int idx = j + i * 256;
                int row = idx >> 6, seg = idx & 63;
                CP_ASYNC16(swo + (c0 * 8 * DD + row * DD + seg * 4) * 4,
                           Wo + (c0 * 8 + row) * DD + seg * 4);
            }
            CP_COMMIT();
        }
        if (isbias) {
            sW[0][j] = bv[j];
        } else {
#pragma unroll
            for (int r = 0; r < 8; r++) sW[r][j] = Wv[(i0 + r) * DD + j];
        }
        __syncthreads();

        float acc[8] = {};
        for (int c = 0; c < 32; c++) {
            if (c + 3 < 32) {
                const int cn = c + 3;
                uint32_t dst = swo + (cn & 3) * 8 * DD * 4;
                const float* src = Wo + cn * 8 * DD;
#pragma unroll
                for (int i = 0; i < 2; i++) {
                    int idx = j + i * 256;
                    int row = idx >> 6, seg = idx & 63;
                    CP_ASYNC16(dst + (row * DD + seg * 4) * 4, src + row * DD + seg * 4);
                }
                CP_COMMIT();
                CP_WAITG(3);
            } else if (c + 2 < 32) {
                CP_WAITG(2);
            } else if (c + 1 < 32) {
                CP_WAITG(1);
            } else {
                CP_WAITG(0);
            }
            __syncthreads();
            const int s = c & 3;
            if (isbias) {
#pragma unroll
                for (int kk = 0; kk < 8; kk++)
                    acc[kk & 3] += sW[0][c * 8 + kk] * sWo[s][kk][j];
            } else {
#pragma unroll
                for (int kk = 0; kk < 8; kk++) {
                    float wo = sWo[s][kk][j];
                    int k = c * 8 + kk;
#pragma unroll
                    for (int r = 0; r < 8; r++) acc[r] += sW[r][k] * wo;
                }
            }
            __syncthreads();
        }
        if (isbias) {
            g_c[j] = (acc[0] + acc[1]) + (acc[2] + acc[3]) + bo[j];
        } else {
#pragma unroll
            for (int r = 0; r < 8; r++)
                g_WTf16[j * DD + i0 + r] = __float2half(acc[r]);
        }
    } else {
        int i = (blk - 33) * 256 + j;
        float4 x = v[i];
        __half2 a = __floats2half2_rn(x.x, x.y);
        __half2 b = __floats2half2_rn(x.z, x.w);
        uint2 pk = {*(uint32_t*)&a, *(uint32_t*)&b};
        ((uint2*)g_valf16)[i] = pk;
    }
}

// ---------------------------------------------------------------------------
// Kernel 2: projection GEMM  V2T = WT @ value^T  (fp16, 128x128 tile)
// ---------------------------------------------------------------------------
#define PKC 64
#define PTILE (128 * 128)
#define PSTAGE (2 * PTILE)
#define PNSTG 3
#define PSMEM (PNSTG * PSTAGE)

__device__ __forceinline__ void pv_load(
    uint32_t st, const __half* A, const __half* B,
    int lda, int ldb, int m0, int n0, int k0, int t) {
#pragma unroll
    for (int i = 0; i < 4; i++) {
        int idx = t + i * 256;
        int row = idx >> 3, seg = idx & 7;
        CP_ASYNC16(st + SWX(row, seg * 16),
                   A + (size_t)(m0 + row) * lda + k0 + seg * 8);
        CP_ASYNC16(st + PTILE + SWX(row, seg * 16),
                   B + (size_t)(n0 + row) * ldb + k0 + seg * 8);
    }
    CP_COMMIT();
}

__global__ void __launch_bounds__(256, 2)
k_proj(const __half* __restrict__ A, const __half* __restrict__ B,
       __half* __restrict__ Ch, int lda, int ldb, int ldc, int Ktot) {
    extern __shared__ char smem[];
    const uint32_t sbase = smem_u32(smem);
    const int t = threadIdx.x;
    const int lane = t & 31, wid = t >> 5;
    const int wm = wid >> 2, wn = wid & 3;
    const int n0 = blockIdx.x * 128;
    const int m0 = blockIdx.y * 128;
    const int NC = Ktot / PKC;

    float acc[4][4][4] = {};

    pv_load(sbase, A, B, lda, ldb, m0, n0, 0, t);
    pv_load(sbase + PSTAGE, A, B, lda, ldb, m0, n0, PKC, t);

    const int lrow = lane & 15;
    const int lcolb = (lane >> 4) * 16;

    for (int c = 0; c < NC; c++) {
        if (c + 2 < NC) {
            pv_load(sbase + ((c + 2) % PNSTG) * PSTAGE, A, B, lda, ldb,
                    m0, n0, (c + 2) * PKC, t);
            CP_WAITG(2);
        } else if (c + 1 < NC) {
            CP_WAITG(1);
        } else {
            CP_WAITG(0);
        }
        __syncthreads();
        uint32_t st = sbase + (c % PNSTG) * PSTAGE;
#pragma unroll
        for (int ks = 0; ks < 4; ks++) {
            const uint32_t kcb = ks * 32 + lcolb;
            uint32_t ah[4][4], bh[2][4];
#pragma unroll
            for (int mf = 0; mf < 4; mf++) {
                int row = wm * 64 + mf * 16 + lrow;
                LDSM4(ah[mf][0], ah[mf][1], ah[mf][2], ah[mf][3], st + SWX(row, kcb));
            }
#pragma unroll
            for (int nf2 = 0; nf2 < 2; nf2++) {
                int row = wn * 32 + nf2 * 16 + lrow;
                LDSM4(bh[nf2][0], bh[nf2][1], bh[nf2][2], bh[nf2][3],
                      st + PTILE + SWX(row, kcb));
            }
#pragma unroll
            for (int nf2 = 0; nf2 < 2; nf2++)
#pragma unroll
                for (int mf = 0; mf < 4; mf++) {
                    MMA_F16(acc[mf][nf2 * 2],     ah[mf], bh[nf2][0], bh[nf2][2]);
                    MMA_F16(acc[mf][nf2 * 2 + 1], ah[mf], bh[nf2][1], bh[nf2][3]);
                }
        }
        __syncthreads();
    }

    const int g = lane >> 2, tc = lane & 3;
#pragma unroll
    for (int mf = 0; mf < 4; mf++) {
        int r = m0 + wm * 64 + mf * 16 + g;
#pragma unroll
        for (int nf = 0; nf < 4; nf++) {
            int cidx = n0 + wn * 32 + nf * 8 + 2 * tc;
            *(__half2*)(Ch + (size_t)r * ldc + cidx) =
                __floats2half2_rn(acc[mf][nf][0], acc[mf][nf][1]);
            *(__half2*)(Ch + (size_t)(r + 8) * ldc + cidx) =
                __floats2half2_rn(acc[mf][nf][2], acc[mf][nf][3]);
        }
    }
}

// ---------------------------------------------------------------------------
// Kernel 3 (FUSED): masked exp + PV GEMM + normalize + bias, one pass.
//   Split prefetch: IN(c+2) issued after the exp phase (overlaps MMA(c));
//   V2(c+2) issued after the MMA phase. Two cp.async groups per chunk.
// ---------------------------------------------------------------------------
#define FM 64
#define FKC 64
#define FNC (LL / FKC)                   // 32
#define FIN_PITCH 272                    // 256B data + 16B skew
#define FIN_TILE (FM * FIN_PITCH)        // 17408
#define FIN_STAGE (3 * FIN_TILE)         // 52224 (atten,mask,pad)
#define FV2_TILE (256 * 128)             // 32768
#define FSTAGE (FIN_STAGE + FV2_TILE)    // 84992
#define FP_TILE (FM * 128)               // 8192
#define FOFF_IN(s)  ((s) * FSTAGE)
#define FOFF_V2(s)  ((s) * FSTAGE + FIN_STAGE)
#define FOFF_P(s)   (2 * FSTAGE + (s) * FP_TILE)
#define FOFF_SUM    (2 * FSTAGE + 2 * FP_TILE)
#define FSMEM       (FOFF_SUM + 256)     // 186624

__device__ __forceinline__ void f_load_in(
    uint32_t sb, const float* at, const float* mk, const int* pd,
    int s, int b, int m0, int k0, int t) {
#pragma unroll
    for (int i = 0; i < 4; i++) {
        int idx = t + i * 256;
        int row = idx >> 4, seg = idx & 15;
        size_t g = ((size_t)b * LL + m0 + row) * LL + k0 + seg * 4;
        uint32_t d = sb + FOFF_IN(s) + row * FIN_PITCH + seg * 16;
        CP_ASYNC16(d, at + g);
        CP_ASYNC16(d + FIN_TILE, mk + g);
        CP_ASYNC16(d + 2 * FIN_TILE, (const float*)pd + g);
    }
    CP_COMMIT();
}

__device__ __forceinline__ void f_load_v2(
    uint32_t sb, const __half* v2t, int s, int b, int k0, int t) {
#pragma unroll
    for (int i = 0; i < 8; i++) {
        int idx = t + i * 256;
        int row = idx >> 3, seg = idx & 7;
        CP_ASYNC16(sb + FOFF_V2(s) + SWX(row, seg * 16),
                   v2t + (size_t)row * (BB * LL) + (size_t)b * LL + k0 + seg * 8);
    }
    CP_COMMIT();
}

__global__ void __launch_bounds__(256, 1)
k_fused(const float* __restrict__ atten, const float* __restrict__ mask,
        const int* __restrict__ pad, const __half* __restrict__ v2t,
        float* __restrict__ out) {
    extern __shared__ char smem[];
    const uint32_t sb = smem_u32(smem);
    const int t = threadIdx.x;
    const int lane = t & 31, wid = t >> 5;
    const int m0 = blockIdx.x * FM;
    const int b  = blockIdx.y;

    float* rowsum = (float*)(smem + FOFF_SUM);
    if (t < FM) rowsum[t] = 0.f;

    // prologue: 4 groups, order IN0, V0, IN1, V1
    f_load_in(sb, atten, mask, pad, 0, b, m0, 0, t);
    f_load_v2(sb, v2t, 0, b, 0, t);
    f_load_in(sb, atten, mask, pad, 1, b, m0, FKC, t);
    f_load_v2(sb, v2t, 1, b, FKC, t);

    float acc[4][4][4] = {};
    const int r  = t >> 2;
    const int cg = t & 3;
    const int lrow = lane & 15;
    const int lcolb = (lane >> 4) * 16;

    for (int c = 0; c < FNC; c++) {
        // need IN(c)+V2(c) done; groups after V2(c) are IN(c+1), V2(c+1)
        if (c + 1 < FNC) { CP_WAITG(2); } else { CP_WAITG(0); }
        __syncthreads();

        // ---- exp phase (consumes IN stage c&1) ----
        {
            const char* ib = smem + FOFF_IN(c & 1) + r * FIN_PITCH + cg * 64;
            float e[16];
            float part = 0.f;
#pragma unroll
            for (int q = 0; q < 4; q++) {
                float4 a  = *(const float4*)(ib + q * 16);
                float4 mk = *(const float4*)(ib + FIN_TILE + q * 16);
                int4   p  = *(const int4*)(ib + 2 * FIN_TILE + q * 16);
                float e0 = (mk.x < 0.5f || p.x == 0) ? 0.f : __expf(a.x);
                float e1 = (mk.y < 0.5f || p.y == 0) ? 0.f : __expf(a.y);
                float e2 = (mk.z < 0.5f || p.z == 0) ? 0.f : __expf(a.z);
                float e3 = (mk.w < 0.5f || p.w == 0) ? 0.f : __expf(a.w);
                e[q * 4 + 0] = e0; e[q * 4 + 1] = e1;
                e[q * 4 + 2] = e2; e[q * 4 + 3] = e3;
                part += (e0 + e1) + (e2 + e3);
            }
            part += __shfl_xor_sync(0xffffffffu, part, 1);
            part += __shfl_xor_sync(0xffffffffu, part, 2);
            if (cg == 0) rowsum[r] += part;
            uint32_t pb = sb + FOFF_P(c & 1);
            uint32_t h[8];
#pragma unroll
            for (int q = 0; q < 8; q++) {
                __half2 hh = __floats2half2_rn(e[q * 2], e[q * 2 + 1]);
                h[q] = *(uint32_t*)&hh;
            }
            uint32_t colb = cg * 32;
            asm volatile("st.shared.v4.b32 [%0], {%1,%2,%3,%4};"
                :: "r"(pb + SWX(r, colb)), "r"(h[0]), "r"(h[1]), "r"(h[2]), "r"(h[3]));
            asm volatile("st.shared.v4.b32 [%0], {%1,%2,%3,%4};"
                :: "r"(pb + SWX(r, colb + 16)), "r"(h[4]), "r"(h[5]), "r"(h[6]), "r"(h[7]));
        }
        __syncthreads();   // P visible; IN stage c&1 fully consumed by all warps

        // IN(c+2) can overwrite IN stage c&1 now — overlaps the MMA below
        if (c + 2 < FNC)
            f_load_in(sb, atten, mask, pad, c & 1, b, m0, (c + 2) * FKC, t);

        // ---- MMA phase (consumes V2 stage c&1) ----
        {
            uint32_t pb = sb + FOFF_P(c & 1);
            uint32_t vb = sb + FOFF_V2(c & 1);
#pragma unroll
            for (int kt = 0; kt < 4; kt++) {
                const uint32_t kcb = kt * 32 + lcolb;
                uint32_t ah[4][4], bh[2][4];
#pragma unroll
                for (int mf = 0; mf < 4; mf++)
                    LDSM4(ah[mf][0], ah[mf][1], ah[mf][2], ah[mf][3],
                          pb + SWX(mf * 16 + lrow, kcb));
#pragma unroll
                for (int nf2 = 0; nf2 < 2; nf2++)
                    LDSM4(bh[nf2][0], bh[nf2][1], bh[nf2][2], bh[nf2][3],
                          vb + SWX(wid * 32 + nf2 * 16 + lrow, kcb));
#pragma unroll
                for (int nf2 = 0; nf2 < 2; nf2++)
#pragma unroll
                    for (int mf = 0; mf < 4; mf++) {
                        MMA_F16(acc[mf][nf2 * 2],     ah[mf], bh[nf2][0], bh[nf2][2]);
                        MMA_F16(acc[mf][nf2 * 2 + 1], ah[mf], bh[nf2][1], bh[nf2][3]);
                    }
            }
        }
        __syncthreads();   // V2 stage c&1 fully consumed

        if (c + 2 < FNC)
            f_load_v2(sb, v2t, c & 1, b, (c + 2) * FKC, t);
    }

    // ---- epilogue ----
    const int g = lane >> 2, tc = lane & 3;
#pragma unroll
    for (int mf = 0; mf < 4; mf++) {
        int rl0 = mf * 16 + g;
        float inv0 = 1.0f / rowsum[rl0];
        float inv1 = 1.0f / rowsum[rl0 + 8];
        size_t o0 = ((size_t)b * LL + m0 + rl0) * DD;
#pragma unroll
        for (int nf = 0; nf < 4; nf++) {
            int col = wid * 32 + nf * 8 + tc * 2;
            float b0 = g_c[col], b1 = g_c[col + 1];
            *(float2*)(out + o0 + col) =
                {acc[mf][nf][0] * inv0 + b0, acc[mf][nf][1] * inv0 + b1};
            *(float2*)(out + o0 + (size_t)8 * DD + col) =
                {acc[mf][nf][2] * inv1 + b0, acc[mf][nf][3] * inv1 + b1};
        }
    }
}

// ---------------------------------------------------------------------------
extern "C" void kernel_launch(void* const* d_in, const int* in_sizes, int n_in,
                              void* d_out, int out_size) {
    const float* atten = (const float*)d_in[0];
    const float* value = (const float*)d_in[1];
    const float* mask  = (const float*)d_in[2];
    const int*   pad   = (const int*)d_in[3];
    const float* Wv    = (const float*)d_in[4];
    const float* bv    = (const float*)d_in[5];
    const float* Wo    = (const float*)d_in[6];
    const float* bo    = (const float*)d_in[7];
    float* out = (float*)d_out;

    void *pWT, *pVal, *pV2;
    cudaGetSymbolAddress(&pWT, g_WTf16);
    cudaGetSymbolAddress(&pVal, g_valf16);
    cudaGetSymbolAddress(&pV2, g_V2Tf16);

    cudaFuncSetAttribute(k_proj, cudaFuncAttributeMaxDynamicSharedMemorySize, PSMEM);
    cudaFuncSetAttribute(k_fused, cudaFuncAttributeMaxDynamicSharedMemorySize, FSMEM);

    // 0: WT fp16 + bias + value->fp16 (4-stage staged Wo)
    k_pre<<<33 + 2048, 256>>>(Wv, Wo, bv, bo, (const float4*)value);
    // 1: V2T = WT @ value^T (M=256, N=8192, K=256)
    k_proj<<<dim3((BB * LL) / 128, DD / 128, 1), 256, PSMEM>>>(
        (const __half*)pWT, (const __half*)pVal, (__half*)pV2,
        DD, DD, BB * LL, DD);
    // 2: fused masked-softmax + PV + bias (split IN/V2 prefetch)
    k_fused<<<dim3(LL / FM, BB), 256, FSMEM>>>(
        atten, mask, pad, (const __half*)pV2, out);
}

// round 16
// speedup vs baseline: 1.0727x; 1.0727x over previous
#include <cuda_runtime.h>
#include <cuda_bf16.h>
#include <cuda_fp16.h>
#include <math.h>
#include <float.h>
#include <stdint.h>

#define BB 4
#define LL 2048
#define DD 256

// ---------------- device scratch (allocation-free rule) ----------------
__device__ float g_c[DD];                              // bv @ Wo + bo
__device__ __half g_WTf16[DD * DD];                    // (Wv@Wo)^T fp16
__device__ __half g_valf16[BB * LL * DD];              // value fp16 [8192][256]
__device__ __half g_V2Tf16[DD * BB * LL];              // V2^T fp16 [256][8192]

// ---------------- helpers ----------------
__device__ __forceinline__ uint32_t smem_u32(const void* p) {
    uint32_t a;
    asm("{ .reg .u64 t; cvta.to.shared.u64 t, %1; cvt.u32.u64 %0, t; }" : "=r"(a) : "l"(p));
    return a;
}
#define CP_ASYNC16(sm, g) \
    asm volatile("cp.async.cg.shared.global [%0], [%1], 16;" :: "r"(sm), "l"(g))
#define CP_COMMIT() asm volatile("cp.async.commit_group;")
#define CP_WAITG(n) asm volatile("cp.async.wait_group %0;" :: "n"(n))

#define LDSM4(r0, r1, r2, r3, addr)                                            \
    asm volatile("ldmatrix.sync.aligned.m8n8.x4.shared.b16 {%0,%1,%2,%3}, [%4];" \
                 : "=r"(r0), "=r"(r1), "=r"(r2), "=r"(r3) : "r"(addr))

#define MMA_F16(d, a, b0, b1)                                                    \
    asm volatile("mma.sync.aligned.m16n8k16.row.col.f32.f16.f16.f32 "            \
                 "{%0,%1,%2,%3},{%4,%5,%6,%7},{%8,%9},{%0,%1,%2,%3};"            \
                 : "+f"((d)[0]), "+f"((d)[1]), "+f"((d)[2]), "+f"((d)[3])        \
                 : "r"((a)[0]), "r"((a)[1]), "r"((a)[2]), "r"((a)[3]),           \
                   "r"(b0), "r"(b1))

#define SWX(row, colb) ((row) * 128 + ((colb) ^ (((row) & 7) << 4)))

// ---------------------------------------------------------------------------
// Kernel 1 (heterogeneous):
//   blocks [0,33):  W rows / bias; Wo streamed through an 8-stage x 8-row
//                   cp.async ring (depth-7 outstanding, fully unrolled).
//   blocks [33,33+2048): value fp32 -> fp16.
//   Dynamic smem: sW 8KB + 8 stages x 8KB = 72KB (wc blocks only).
// ---------------------------------------------------------------------------
#define PRE_SMEM (8192 + 8 * 8 * DD * 4)   // 73728

__global__ void k_pre(const float* __restrict__ Wv, const float* __restrict__ Wo,
                      const float* __restrict__ bv, const float* __restrict__ bo,
                      const float4* __restrict__ v) {
    extern __shared__ char psm[];
    const int blk = blockIdx.x;
    const int j = threadIdx.x;
    if (blk < 33) {
        float* sW  = (float*)psm;                  // [8][256]
        float* sWo = (float*)(psm + 8192);         // [8][8][256]
        const uint32_t swo = smem_u32(sWo);
        const bool isbias = (blk == 32);
        const int i0 = blk * 8;

        // prologue: stage chunks 0..6 (8 rows x 1KB each; 2 x 16B per thread)
#pragma unroll
        for (int c0 = 0; c0 < 7; c0++) {
#pragma unroll
            for (int i = 0; i < 2; i++) {
                int idx = j + i * 256;
                int row = idx >> 6, seg = idx & 63;
                CP_ASYNC16(swo + (c0 * 2048 + row * 256 + seg * 4) * 4,
                           Wo + (c0 * 8 + row) * DD + seg * 4);
            }
            CP_COMMIT();
        }
        if (isbias) {
            sW[j] = bv[j];
        } else {
#pragma unroll
            for (int r = 0; r < 8; r++) sW[r * DD + j] = Wv[(i0 + r) * DD + j];
        }
        __syncthreads();

        float acc[8] = {};
#pragma unroll
        for (int c = 0; c < 32; c++) {
            if (c + 7 < 32) {
                const int cn = c + 7;
#pragma unroll
                for (int i = 0; i < 2; i++) {
                    int idx = j + i * 256;
                    int row = idx >> 6, seg = idx & 63;
                    CP_ASYNC16(swo + ((cn & 7) * 2048 + row * 256 + seg * 4) * 4,
                               Wo + (cn * 8 + row) * DD + seg * 4);
                }
                CP_COMMIT();
                CP_WAITG(7);
            } else if (c + 6 < 32) { CP_WAITG(6); }
            else if (c + 5 < 32) { CP_WAITG(5); }
            else if (c + 4 < 32) { CP_WAITG(4); }
            else if (c + 3 < 32) { CP_WAITG(3); }
            else if (c + 2 < 32) { CP_WAITG(2); }
            else if (c + 1 < 32) { CP_WAITG(1); }
            else { CP_WAITG(0); }
            __syncthreads();
            const float* st = sWo + (c & 7) * 2048;
            if (isbias) {
#pragma unroll
                for (int kk = 0; kk < 8; kk++)
                    acc[kk & 3] += sW[c * 8 + kk] * st[kk * 256 + j];
            } else {
#pragma unroll
                for (int kk = 0; kk < 8; kk++) {
                    float wo = st[kk * 256 + j];
                    int k = c * 8 + kk;
#pragma unroll
                    for (int r = 0; r < 8; r++) acc[r] += sW[r * DD + k] * wo;
                }
            }
            __syncthreads();
        }
        if (isbias) {
            g_c[j] = (acc[0] + acc[1]) + (acc[2] + acc[3]) + bo[j];
        } else {
#pragma unroll
            for (int r = 0; r < 8; r++)
                g_WTf16[j * DD + i0 + r] = __float2half(acc[r]);
        }
    } else {
        int i = (blk - 33) * 256 + j;
        float4 x = v[i];
        __half2 a = __floats2half2_rn(x.x, x.y);
        __half2 b = __floats2half2_rn(x.z, x.w);
        uint2 pk = {*(uint32_t*)&a, *(uint32_t*)&b};
        ((uint2*)g_valf16)[i] = pk;
    }
}

// ---------------------------------------------------------------------------
// Kernel 2: projection GEMM  V2T = WT @ value^T  (fp16, 128x128 tile)
// ---------------------------------------------------------------------------
#define PKC 64
#define PTILE (128 * 128)
#define PSTAGE (2 * PTILE)
#define PNSTG 3
#define PSMEM (PNSTG * PSTAGE)

__device__ __forceinline__ void pv_load(
    uint32_t st, const __half* A, const __half* B,
    int lda, int ldb, int m0, int n0, int k0, int t) {
#pragma unroll
    for (int i = 0; i < 4; i++) {
        int idx = t + i * 256;
        int row = idx >> 3, seg = idx & 7;
        CP_ASYNC16(st + SWX(row, seg * 16),
                   A + (size_t)(m0 + row) * lda + k0 + seg * 8);
        CP_ASYNC16(st + PTILE + SWX(row, seg * 16),
                   B + (size_t)(n0 + row) * ldb + k0 + seg * 8);
    }
    CP_COMMIT();
}

__global__ void __launch_bounds__(256, 2)
k_proj(const __half* __restrict__ A, const __half* __restrict__ B,
       __half* __restrict__ Ch, int lda, int ldb, int ldc, int Ktot) {
    extern __shared__ char smem[];
    const uint32_t sbase = smem_u32(smem);
    const int t = threadIdx.x;
    const int lane = t & 31, wid = t >> 5;
    const int wm = wid >> 2, wn = wid & 3;
    const int n0 = blockIdx.x * 128;
    const int m0 = blockIdx.y * 128;
    const int NC = Ktot / PKC;

    float acc[4][4][4] = {};

    pv_load(sbase, A, B, lda, ldb, m0, n0, 0, t);
    pv_load(sbase + PSTAGE, A, B, lda, ldb, m0, n0, PKC, t);

    const int lrow = lane & 15;
    const int lcolb = (lane >> 4) * 16;

    for (int c = 0; c < NC; c++) {
        if (c + 2 < NC) {
            pv_load(sbase + ((c + 2) % PNSTG) * PSTAGE, A, B, lda, ldb,
                    m0, n0, (c + 2) * PKC, t);
            CP_WAITG(2);
        } else if (c + 1 < NC) {
            CP_WAITG(1);
        } else {
            CP_WAITG(0);
        }
        __syncthreads();
        uint32_t st = sbase + (c % PNSTG) * PSTAGE;
#pragma unroll
        for (int ks = 0; ks < 4; ks++) {
            const uint32_t kcb = ks * 32 + lcolb;
            uint32_t ah[4][4], bh[2][4];
#pragma unroll
            for (int mf = 0; mf < 4; mf++) {
                int row = wm * 64 + mf * 16 + lrow;
                LDSM4(ah[mf][0], ah[mf][1], ah[mf][2], ah[mf][3], st + SWX(row, kcb));
            }
#pragma unroll
            for (int nf2 = 0; nf2 < 2; nf2++) {
                int row = wn * 32 + nf2 * 16 + lrow;
                LDSM4(bh[nf2][0], bh[nf2][1], bh[nf2][2], bh[nf2][3],
                      st + PTILE + SWX(row, kcb));
            }
#pragma unroll
            for (int nf2 = 0; nf2 < 2; nf2++)
#pragma unroll
                for (int mf = 0; mf < 4; mf++) {
                    MMA_F16(acc[mf][nf2 * 2],     ah[mf], bh[nf2][0], bh[nf2][2]);
                    MMA_F16(acc[mf][nf2 * 2 + 1], ah[mf], bh[nf2][1], bh[nf2][3]);
                }
        }
        __syncthreads();
    }

    const int g = lane >> 2, tc = lane & 3;
#pragma unroll
    for (int mf = 0; mf < 4; mf++) {
        int r = m0 + wm * 64 + mf * 16 + g;
#pragma unroll
        for (int nf = 0; nf < 4; nf++) {
            int cidx = n0 + wn * 32 + nf * 8 + 2 * tc;
            *(__half2*)(Ch + (size_t)r * ldc + cidx) =
                __floats2half2_rn(acc[mf][nf][0], acc[mf][nf][1]);
            *(__half2*)(Ch + (size_t)(r + 8) * ldc + cidx) =
                __floats2half2_rn(acc[mf][nf][2], acc[mf][nf][3]);
        }
    }
}

// ---------------------------------------------------------------------------
// Kernel 3 (FUSED v2): exp phase reads atten/mask/pad DIRECTLY from gmem
//   (no smem staging), writes only P(fp16) to smem. V2 stays cp.async
//   double-buffered. FM=32 rows/CTA -> grid 256, 2 CTAs/SM, 2 barriers/chunk.
// ---------------------------------------------------------------------------
#define FM 32
#define FKC 64
#define FNC (LL / FKC)                      // 32
#define FV2_TILE (256 * 128)                // 32768
#define FP_TILE (FM * 128)                  // 4096
#define FOFF_V2(s) ((s) * FV2_TILE)
#define FOFF_P(s)  (2 * FV2_TILE + (s) * FP_TILE)
#define FOFF_SUM   (2 * FV2_TILE + 2 * FP_TILE)
#define FSMEM      (FOFF_SUM + 128)         // 73856

__device__ __forceinline__ void f_load_v2(
    uint32_t sb, const __half* v2t, int s, int b, int k0, int t) {
#pragma unroll
    for (int i = 0; i < 8; i++) {
        int idx = t + i * 256;
        int row = idx >> 3, seg = idx & 7;
        CP_ASYNC16(sb + FOFF_V2(s) + SWX(row, seg * 16),
                   v2t + (size_t)row * (BB * LL) + (size_t)b * LL + k0 + seg * 8);
    }
    CP_COMMIT();
}

__global__ void __launch_bounds__(256, 2)
k_fused(const float* __restrict__ atten, const float* __restrict__ mask,
        const int* __restrict__ pad, const __half* __restrict__ v2t,
        float* __restrict__ out) {
    extern __shared__ char smem[];
    const uint32_t sb = smem_u32(smem);
    const int t = threadIdx.x;
    const int lane = t & 31, wid = t >> 5;
    const int m0 = blockIdx.x * FM;
    const int b  = blockIdx.y;

    float* rowsum = (float*)(smem + FOFF_SUM);
    if (t < FM) rowsum[t] = 0.f;

    f_load_v2(sb, v2t, 0, b, 0, t);
    f_load_v2(sb, v2t, 1, b, FKC, t);
    __syncthreads();                         // rowsum init visible

    float acc[2][4][4] = {};
    const int r  = t >> 3;                   // 0..31 (exp row)
    const int cg = t & 7;                    // 8 col-groups x 8 elems
    const int lrow = lane & 15;
    const int lcolb = (lane >> 4) * 16;

    // per-thread gmem base for exp phase
    const size_t grow = ((size_t)b * LL + m0 + r) * LL + cg * 8;

    for (int c = 0; c < FNC; c++) {
        // ---- exp phase: direct gmem reads, P -> smem ----
        {
            const float4* a4 = (const float4*)(atten + grow + c * FKC);
            const float4* m4 = (const float4*)(mask  + grow + c * FKC);
            const int4*   p4 = (const int4*)(pad    + grow + c * FKC);
            float4 a0 = a4[0], a1 = a4[1];
            float4 k0 = m4[0], k1 = m4[1];
            int4   q0 = p4[0], q1 = p4[1];
            float e[8];
            e[0] = (k0.x < 0.5f || q0.x == 0) ? 0.f : __expf(a0.x);
            e[1] = (k0.y < 0.5f || q0.y == 0) ? 0.f : __expf(a0.y);
            e[2] = (k0.z < 0.5f || q0.z == 0) ? 0.f : __expf(a0.z);
            e[3] = (k0.w < 0.5f || q0.w == 0) ? 0.f : __expf(a0.w);
            e[4] = (k1.x < 0.5f || q1.x == 0) ? 0.f : __expf(a1.x);
            e[5] = (k1.y < 0.5f || q1.y == 0) ? 0.f : __expf(a1.y);
            e[6] = (k1.z < 0.5f || q1.z == 0) ? 0.f : __expf(a1.z);
            e[7] = (k1.w < 0.5f || q1.w == 0) ? 0.f : __expf(a1.w);
            float part = ((e[0] + e[1]) + (e[2] + e[3])) +
                         ((e[4] + e[5]) + (e[6] + e[7]));
            part += __shfl_xor_sync(0xffffffffu, part, 1);
            part += __shfl_xor_sync(0xffffffffu, part, 2);
            part += __shfl_xor_sync(0xffffffffu, part, 4);
            if (cg == 0) rowsum[r] += part;
            __half2 h0 = __floats2half2_rn(e[0], e[1]);
            __half2 h1 = __floats2half2_rn(e[2], e[3]);
            __half2 h2 = __floats2half2_rn(e[4], e[5]);
            __half2 h3 = __floats2half2_rn(e[6], e[7]);
            asm volatile("st.shared.v4.b32 [%0], {%1,%2,%3,%4};"
                :: "r"(sb + FOFF_P(c & 1) + SWX(r, cg * 16)),
                   "r"(*(uint32_t*)&h0), "r"(*(uint32_t*)&h1),
                   "r"(*(uint32_t*)&h2), "r"(*(uint32_t*)&h3));
        }
        if (c + 1 < FNC) { CP_WAITG(1); } else { CP_WAITG(0); }
        __syncthreads();                     // P + V2(c) visible

        // ---- MMA phase ----
        {
            uint32_t pb = sb + FOFF_P(c & 1);
            uint32_t vb = sb + FOFF_V2(c & 1);
#pragma unroll
            for (int kt = 0; kt < 4; kt++) {
                const uint32_t kcb = kt * 32 + lcolb;
                uint32_t ah[2][4], bh[2][4];
#pragma unroll
                for (int mf = 0; mf < 2; mf++)
                    LDSM4(ah[mf][0], ah[mf][1], ah[mf][2], ah[mf][3],
                          pb + SWX(mf * 16 + lrow, kcb));
#pragma unroll
                for (int nf2 = 0; nf2 < 2; nf2++)
                    LDSM4(bh[nf2][0], bh[nf2][1], bh[nf2][2], bh[nf2][3],
                          vb + SWX(wid * 32 + nf2 * 16 + lrow, kcb));
#pragma unroll
                for (int nf2 = 0; nf2 < 2; nf2++)
#pragma unroll
                    for (int mf = 0; mf < 2; mf++) {
                        MMA_F16(acc[mf][nf2 * 2],     ah[mf], bh[nf2][0], bh[nf2][2]);
                        MMA_F16(acc[mf][nf2 * 2 + 1], ah[mf], bh[nf2][1], bh[nf2][3]);
                    }
            }
        }
        __syncthreads();                     // V2 + P stage consumable

        if (c + 2 < FNC)
            f_load_v2(sb, v2t, c & 1, b, (c + 2) * FKC, t);
    }

    // ---- epilogue: out = acc / rowsum + c ----
    const int g = lane >> 2, tc = lane & 3;
#pragma unroll
    for (int mf = 0; mf < 2; mf++) {
        int rl0 = mf * 16 + g;
        float inv0 = 1.0f / rowsum[rl0];
        float inv1 = 1.0f / rowsum[rl0 + 8];
        size_t o0 = ((size_t)b * LL + m0 + rl0) * DD;
#pragma unroll
        for (int nf = 0; nf < 4; nf++) {
            int col = wid * 32 + nf * 8 + tc * 2;
            float b0 = g_c[col], b1 = g_c[col + 1];
            *(float2*)(out + o0 + col) =
                {acc[mf][nf][0] * inv0 + b0, acc[mf][nf][1] * inv0 + b1};
            *(float2*)(out + o0 + (size_t)8 * DD + col) =
                {acc[mf][nf][2] * inv1 + b0, acc[mf][nf][3] * inv1 + b1};
        }
    }
}

// ---------------------------------------------------------------------------
extern "C" void kernel_launch(void* const* d_in, const int* in_sizes, int n_in,
                              void* d_out, int out_size) {
    const float* atten = (const float*)d_in[0];
    const float* value = (const float*)d_in[1];
    const float* mask  = (const float*)d_in[2];
    const int*   pad   = (const int*)d_in[3];
    const float* Wv    = (const float*)d_in[4];
    const float* bv    = (const float*)d_in[5];
    const float* Wo    = (const float*)d_in[6];
    const float* bo    = (const float*)d_in[7];
    float* out = (float*)d_out;

    void *pWT, *pVal, *pV2;
    cudaGetSymbolAddress(&pWT, g_WTf16);
    cudaGetSymbolAddress(&pVal, g_valf16);
    cudaGetSymbolAddress(&pV2, g_V2Tf16);

    cudaFuncSetAttribute(k_pre, cudaFuncAttributeMaxDynamicSharedMemorySize, PRE_SMEM);
    cudaFuncSetAttribute(k_proj, cudaFuncAttributeMaxDynamicSharedMemorySize, PSMEM);
    cudaFuncSetAttribute(k_fused, cudaFuncAttributeMaxDynamicSharedMemorySize, FSMEM);

    // 0: WT fp16 + bias + value->fp16 (8-stage Wo ring)
    k_pre<<<33 + 2048, 256, PRE_SMEM>>>(Wv, Wo, bv, bo, (const float4*)value);
    // 1: V2T = WT @ value^T (M=256, N=8192, K=256)
    k_proj<<<dim3((BB * LL) / 128, DD / 128, 1), 256, PSMEM>>>(
        (const __half*)pWT, (const __half*)pVal, (__half*)pV2,
        DD, DD, BB * LL, DD);
    // 2: fused masked-softmax + PV + bias (direct-gmem exp, 2 CTA/SM)
    k_fused<<<dim3(LL / FM, BB), 256, FSMEM>>>(
        atten, mask, pad, (const __half*)pV2, out);
}